// round 6
// baseline (speedup 1.0000x reference)
#include <cuda_runtime.h>
#include <cuda_bf16.h>

// ---------------------------------------------------------------------------
// NDCG loss, N = 16,777,216 (general N supported up to MAXG*EPB).
// Pass 1: score (float4 loads) -> bitmask in strided-nibble layout + counts.
//         Word (group j, comp c), bit l  <->  element j*128 + l*4 + c.
// Pass 2: predict + bitmask -> unified branch-free term, one RCP per 4 elems.
// Pass 3: deterministic reduction of partials -> d_out[0].
// ---------------------------------------------------------------------------

#define EPB 8192            // elements per block (256 thr * 32 elem)
#define EPW 1024            // elements per warp
#define MAXG 4096           // max blocks supported by static scratch

__device__ unsigned int g_mask[MAXG * 256];   // 1 bit per element (strided)
__device__ int          g_counts[MAXG];       // positives per block
__device__ float        g_partials[MAXG];     // per-block loss partials

// ---------------------------------------------------------------------------
__global__ __launch_bounds__(256) void k_mask(const float* __restrict__ score,
                                              int N) {
    const int warp = threadIdx.x >> 5, lane = threadIdx.x & 31;
    const int base = blockIdx.x * EPB + warp * EPW;

    // 8 groups of 128 elements per warp. Lane L loads elements L*4..L*4+3 of
    // each group as float4. Ballot per nibble-bit builds 4 words per group.
    // Lane (4j+c) keeps word (j,c).
    unsigned myword = 0;
    #pragma unroll
    for (int jb = 0; jb < 8; jb += 4) {
        float4 v[4];
        #pragma unroll
        for (int t = 0; t < 4; ++t) {
            int e0 = base + (jb + t) * 128 + lane * 4;
            if (e0 + 3 < N) {
                v[t] = *reinterpret_cast<const float4*>(score + e0);
            } else {
                v[t].x = (e0     < N) ? score[e0]     : 0.0f;
                v[t].y = (e0 + 1 < N) ? score[e0 + 1] : 0.0f;
                v[t].z = (e0 + 2 < N) ? score[e0 + 2] : 0.0f;
                v[t].w = (e0 + 3 < N) ? score[e0 + 3] : 0.0f;
            }
        }
        #pragma unroll
        for (int t = 0; t < 4; ++t) {
            const int j = jb + t;
            unsigned b0 = __ballot_sync(0xffffffffu, v[t].x > 0.0f);
            unsigned b1 = __ballot_sync(0xffffffffu, v[t].y > 0.0f);
            unsigned b2 = __ballot_sync(0xffffffffu, v[t].z > 0.0f);
            unsigned b3 = __ballot_sync(0xffffffffu, v[t].w > 0.0f);
            if (lane == j * 4 + 0) myword = b0;
            if (lane == j * 4 + 1) myword = b1;
            if (lane == j * 4 + 2) myword = b2;
            if (lane == j * 4 + 3) myword = b3;
        }
    }
    g_mask[(blockIdx.x << 8) + (warp << 5) + lane] = myword;

    int c = __popc(myword);
    #pragma unroll
    for (int o = 16; o; o >>= 1) c += __shfl_xor_sync(0xffffffffu, c, o);

    __shared__ int sc[8];
    if (lane == 0) sc[warp] = c;
    __syncthreads();
    if (threadIdx.x == 0) {
        int t = 0;
        #pragma unroll
        for (int w = 0; w < 8; ++w) t += sc[w];
        g_counts[blockIdx.x] = t;
    }
}

// ---------------------------------------------------------------------------
__global__ __launch_bounds__(256) void k_loss(const float* __restrict__ pred,
                                              int N, int G) {
    const int tid  = threadIdx.x;
    const int warp = tid >> 5, lane = tid & 31;

    // --- exclusive block prefix of positives + total P (L2-hot counts) ---
    int pre = 0, tot = 0;
    for (int i = tid; i < G; i += 256) {
        int c = g_counts[i];
        tot += c;
        pre += (i < (int)blockIdx.x) ? c : 0;
    }
    #pragma unroll
    for (int o = 16; o; o >>= 1) {
        pre += __shfl_xor_sync(0xffffffffu, pre, o);
        tot += __shfl_xor_sync(0xffffffffu, tot, o);
    }
    __shared__ int spre[8], stot[8], wsum[8];
    if (lane == 0) { spre[warp] = pre; stot[warp] = tot; }
    __syncthreads();
    int blockPre = 0, P = 0;
    #pragma unroll
    for (int w = 0; w < 8; ++w) { blockPre += spre[w]; P += stot[w]; }

    // --- per-warp mask words; exclusive word-prefix of popcounts ---
    const int base = blockIdx.x * EPB + warp * EPW;
    unsigned myword = g_mask[(blockIdx.x << 8) + (warp << 5) + lane];
    int wc  = __popc(myword);
    int inc = wc;
    #pragma unroll
    for (int o = 1; o < 32; o <<= 1) {
        int t = __shfl_up_sync(0xffffffffu, inc, o);
        if (lane >= o) inc += t;
    }
    int exc = inc - wc;                 // popcount of words before 'lane'
    if (lane == 31) wsum[warp] = inc;   // warp total
    __syncthreads();
    int warpBase = blockPre;
    for (int w = 0; w < warp; ++w) warpBase += wsum[w];

    const float Pf    = (float)P;
    const float invP  = 1.0f / Pf;          // s value at positives
    const float sum_s = Pf * invP;          // ~= 1.0 (faithful to reference)
    const float rp    = 1.0f / sum_s;
    const unsigned lm = (1u << lane) - 1u;  // bits below this lane

    float acc = 0.0f;

    #pragma unroll
    for (int jb = 0; jb < 8; jb += 4) {
        float4 pv[4];
        #pragma unroll
        for (int t = 0; t < 4; ++t) {
            int e0 = base + (jb + t) * 128 + lane * 4;
            if (e0 + 3 < N) {
                pv[t] = *reinterpret_cast<const float4*>(pred + e0);
            } else {
                pv[t].x = (e0     < N) ? pred[e0]     : 0.0f;
                pv[t].y = (e0 + 1 < N) ? pred[e0 + 1] : 0.0f;
                pv[t].z = (e0 + 2 < N) ? pred[e0 + 2] : 0.0f;
                pv[t].w = (e0 + 3 < N) ? pred[e0 + 3] : 0.0f;
            }
        }
        #pragma unroll
        for (int t = 0; t < 4; ++t) {
            const int j  = jb + t;
            const int e0 = base + j * 128 + lane * 4;
            // 4 mask words of this group (strided layout)
            const unsigned w0 = __shfl_sync(0xffffffffu, myword, j * 4 + 0);
            const unsigned w1 = __shfl_sync(0xffffffffu, myword, j * 4 + 1);
            const unsigned w2 = __shfl_sync(0xffffffffu, myword, j * 4 + 2);
            const unsigned w3 = __shfl_sync(0xffffffffu, myword, j * 4 + 3);
            const int gbase   = __shfl_sync(0xffffffffu, exc, j * 4); // pos before group
            // positives inside group before element (lane,0):
            const int inBase = __popc(w0 & lm) + __popc(w1 & lm) +
                               __popc(w2 & lm) + __popc(w3 & lm);
            const int kb = warpBase + gbase + inBase;
            const int p0 = (w0 >> lane) & 1, p1 = (w1 >> lane) & 1,
                      p2 = (w2 >> lane) & 1, p3 = (w3 >> lane) & 1;
            const int kbv[4] = {kb, kb + p0, kb + p0 + p1, kb + p0 + p1 + p2};
            const int pb [4] = {p0, p1, p2, p3};
            const float pvals[4] = {pv[t].x, pv[t].y, pv[t].z, pv[t].w};

            // Unified term, 4-way combined reciprocal:
            //  pos: A=k+1 (k inclusive), C=log2(A), num=p*C-invP*A, d=num/(A*C)
            //  neg: A=P+m+1,            C=1,       num=p,          d=num/A
            float Av[4], Cv[4], Dv[4], nv[4];
            #pragma unroll
            for (int c = 0; c < 4; ++c) {
                const int idx = e0 + c;
                const bool pos = pb[c];
                const float p = pvals[c] * rp;
                const float A = pos ? (float)(kbv[c] + 2)
                                    : (Pf + (float)(idx + 2 - kbv[c]));
                const float C = pos ? __log2f(A) : 1.0f;
                const float sel = pos ? invP : 0.0f;
                Av[c] = A; Cv[c] = C;
                Dv[c] = A * C;
                nv[c] = p * C - sel * A;
            }
            const float D01 = Dv[0] * Dv[1];
            const float D23 = Dv[2] * Dv[3];
            const float r   = __fdividef(1.0f, D01 * D23);
            const float t0 = nv[0] * (Dv[1] * D23) * r;
            const float t1 = nv[1] * (Dv[0] * D23) * r;
            const float t2 = nv[2] * (D01 * Dv[3]) * r;
            const float t3 = nv[3] * (D01 * Dv[2]) * r;
            if (e0     < N) acc += t0 * t0;
            if (e0 + 1 < N) acc += t1 * t1;
            if (e0 + 2 < N) acc += t2 * t2;
            if (e0 + 3 < N) acc += t3 * t3;
        }
    }

    #pragma unroll
    for (int o = 16; o; o >>= 1) acc += __shfl_xor_sync(0xffffffffu, acc, o);
    __shared__ float sacc[8];
    if (lane == 0) sacc[warp] = acc;
    __syncthreads();
    if (tid == 0) {
        float t = 0.0f;
        #pragma unroll
        for (int w = 0; w < 8; ++w) t += sacc[w];
        g_partials[blockIdx.x] = t;
    }
}

// ---------------------------------------------------------------------------
__global__ __launch_bounds__(256) void k_final(float* __restrict__ out, int G) {
    int tid = threadIdx.x;
    float a = 0.0f;
    for (int i = tid; i < G; i += 256) a += g_partials[i];
    #pragma unroll
    for (int o = 16; o; o >>= 1) a += __shfl_xor_sync(0xffffffffu, a, o);
    __shared__ float s[8];
    if ((tid & 31) == 0) s[tid >> 5] = a;
    __syncthreads();
    if (tid == 0) {
        float t = 0.0f;
        #pragma unroll
        for (int w = 0; w < 8; ++w) t += s[w];
        out[0] = t;
    }
}

// ---------------------------------------------------------------------------
extern "C" void kernel_launch(void* const* d_in, const int* in_sizes, int n_in,
                              void* d_out, int out_size) {
    const float* pred  = (const float*)d_in[0];  // predict_score
    const float* score = (const float*)d_in[1];  // score (0/1)
    int N = in_sizes[0];
    int G = (N + EPB - 1) / EPB;
    if (G > MAXG) G = MAXG;   // problem size is 2^24 -> G = 2048

    k_mask<<<G, 256>>>(score, N);
    k_loss<<<G, 256>>>(pred, N, G);
    k_final<<<1, 256>>>((float*)d_out, G);
}

// round 7
// speedup vs baseline: 1.0994x; 1.0994x over previous
#include <cuda_runtime.h>
#include <cuda_bf16.h>

// ---------------------------------------------------------------------------
// NDCG loss, N = 16,777,216 (general N supported up to MAXG*EPB).
// Pass 1: score -> per-32-elem bitmask + per-block positive counts. (R4 ver.)
// Pass 2: predict + bitmask -> unified branch-free term; ranks tracked in
//         float registers (no per-element I2F).
// Pass 3: deterministic reduction of partials -> d_out[0].
// ---------------------------------------------------------------------------

#define EPB 8192            // elements per block (256 thr * 32 elem)
#define EPW 1024            // elements per warp
#define MAXG 4096           // max blocks supported by static scratch

__device__ unsigned int g_mask[MAXG * 256];   // 1 bit per element
__device__ int          g_counts[MAXG];       // positives per block
__device__ float        g_partials[MAXG];     // per-block loss partials

// ---------------------------------------------------------------------------
__global__ __launch_bounds__(256) void k_mask(const float* __restrict__ score,
                                              int N) {
    const int warp = threadIdx.x >> 5, lane = threadIdx.x & 31;
    const int base = blockIdx.x * EPB + warp * EPW;

    // Warp covers EPW=1024 elements -> 32 mask words; lane L owns word L.
    // Loads batched 8 at a time.
    unsigned myword = 0;
    #pragma unroll
    for (int j0 = 0; j0 < 32; j0 += 8) {
        float v[8];
        #pragma unroll
        for (int t = 0; t < 8; ++t) {
            int idx = base + (j0 + t) * 32 + lane;
            v[t] = (idx < N) ? score[idx] : 0.0f;
        }
        #pragma unroll
        for (int t = 0; t < 8; ++t) {
            unsigned b = __ballot_sync(0xffffffffu, v[t] > 0.0f);
            if (lane == j0 + t) myword = b;
        }
    }
    g_mask[(blockIdx.x << 8) + (warp << 5) + lane] = myword;

    int c = __popc(myword);
    #pragma unroll
    for (int o = 16; o; o >>= 1) c += __shfl_xor_sync(0xffffffffu, c, o);

    __shared__ int sc[8];
    if (lane == 0) sc[warp] = c;
    __syncthreads();
    if (threadIdx.x == 0) {
        int t = 0;
        #pragma unroll
        for (int w = 0; w < 8; ++w) t += sc[w];
        g_counts[blockIdx.x] = t;
    }
}

// ---------------------------------------------------------------------------
__global__ __launch_bounds__(256) void k_loss(const float* __restrict__ pred,
                                              int N, int G) {
    const int tid  = threadIdx.x;
    const int warp = tid >> 5, lane = tid & 31;

    // --- exclusive block prefix of positives + total P (L2-hot counts) ---
    int pre = 0, tot = 0;
    for (int i = tid; i < G; i += 256) {
        int c = g_counts[i];
        tot += c;
        pre += (i < (int)blockIdx.x) ? c : 0;
    }
    #pragma unroll
    for (int o = 16; o; o >>= 1) {
        pre += __shfl_xor_sync(0xffffffffu, pre, o);
        tot += __shfl_xor_sync(0xffffffffu, tot, o);
    }
    __shared__ int spre[8], stot[8], wsum[8];
    if (lane == 0) { spre[warp] = pre; stot[warp] = tot; }
    __syncthreads();
    int blockPre = 0, P = 0;
    #pragma unroll
    for (int w = 0; w < 8; ++w) { blockPre += spre[w]; P += stot[w]; }

    // --- per-warp mask words + intra-warp positive prefix via popc scan ---
    const int base = blockIdx.x * EPB + warp * EPW;
    unsigned myword = g_mask[(blockIdx.x << 8) + (warp << 5) + lane];
    int wc  = __popc(myword);
    int inc = wc;
    #pragma unroll
    for (int o = 1; o < 32; o <<= 1) {
        int t = __shfl_up_sync(0xffffffffu, inc, o);
        if (lane >= o) inc += t;
    }
    int exc = inc - wc;                 // positives before word 'lane' in warp
    if (lane == 31) wsum[warp] = inc;   // warp total
    __syncthreads();
    int warpBase = blockPre;
    for (int w = 0; w < warp; ++w) warpBase += wsum[w];

    const float Pf    = (float)P;
    const float invP  = 1.0f / Pf;          // s value at positives
    const float sum_s = Pf * invP;          // ~= 1.0 (faithful to reference)
    const float rp    = 1.0f / sum_s;
    const float basef = (float)base;        // hoisted I2F
    const float lane4f = (float)(lane * 4);

    float acc = 0.0f;

    // Process 8 groups of 128 elems; pred loads batched 4 float4 at a time.
    #pragma unroll
    for (int jb = 0; jb < 8; jb += 4) {
        float4 pv[4];
        #pragma unroll
        for (int t = 0; t < 4; ++t) {
            int e0 = base + (jb + t) * 128 + lane * 4;
            if (e0 + 3 < N) {
                pv[t] = *reinterpret_cast<const float4*>(pred + e0);
            } else {
                pv[t].x = (e0     < N) ? pred[e0]     : 0.0f;
                pv[t].y = (e0 + 1 < N) ? pred[e0 + 1] : 0.0f;
                pv[t].z = (e0 + 2 < N) ? pred[e0 + 2] : 0.0f;
                pv[t].w = (e0 + 3 < N) ? pred[e0 + 3] : 0.0f;
            }
        }
        #pragma unroll
        for (int t = 0; t < 4; ++t) {
            const int j  = jb + t;
            const int e0 = base + j * 128 + lane * 4;
            const int wl = j * 4 + (lane >> 3);      // word covering these elems
            const unsigned w = __shfl_sync(0xffffffffu, myword, wl);
            const int pe     = __shfl_sync(0xffffffffu, exc,    wl);
            const int bit0   = (lane & 7) * 4;
            const int kbase  = warpBase + pe + __popc(w & ((1u << bit0) - 1u));
            const float pvals[4] = {pv[t].x, pv[t].y, pv[t].z, pv[t].w};

            // Float-tracked ranks: one I2F per quad.
            float kbf = (float)kbase;                 // exclusive positive cnt
            // Pbase_c = P + idx(c) + 2 where idx(c) = e0 + c
            const float Pb0 = Pf + basef + (float)(j * 128) + lane4f + 2.0f;

            #pragma unroll
            for (int c = 0; c < 4; ++c) {
                const int idx = e0 + c;
                const bool pos = (w >> (bit0 + c)) & 1u;
                const float posf = pos ? 1.0f : 0.0f;
                const float p = pvals[c] * rp;
                // pos: A = k+1 = kbf+2 (inclusive), C = log2(A), sel = invP
                //      d = (p*C - invP*A)/(A*C) = p/(k+1) - invP/log2(k+1)
                // neg: A = P+m+1 = (P+idx+2) - kbf, C = 1, sel = 0 -> d = p/A
                const float A   = pos ? (kbf + 2.0f)
                                      : ((Pb0 + (float)c) - kbf);
                const float C   = pos ? __log2f(A) : 1.0f;
                const float sel = pos ? invP : 0.0f;
                const float num = p * C - sel * A;
                const float d   = __fdividef(num, A * C);
                if (idx < N) acc += d * d;
                kbf += posf;
            }
        }
    }

    #pragma unroll
    for (int o = 16; o; o >>= 1) acc += __shfl_xor_sync(0xffffffffu, acc, o);
    __shared__ float sacc[8];
    if (lane == 0) sacc[warp] = acc;
    __syncthreads();
    if (tid == 0) {
        float t = 0.0f;
        #pragma unroll
        for (int w = 0; w < 8; ++w) t += sacc[w];
        g_partials[blockIdx.x] = t;
    }
}

// ---------------------------------------------------------------------------
__global__ __launch_bounds__(256) void k_final(float* __restrict__ out, int G) {
    int tid = threadIdx.x;
    float a = 0.0f;
    for (int i = tid; i < G; i += 256) a += g_partials[i];
    #pragma unroll
    for (int o = 16; o; o >>= 1) a += __shfl_xor_sync(0xffffffffu, a, o);
    __shared__ float s[8];
    if ((tid & 31) == 0) s[tid >> 5] = a;
    __syncthreads();
    if (tid == 0) {
        float t = 0.0f;
        #pragma unroll
        for (int w = 0; w < 8; ++w) t += s[w];
        out[0] = t;
    }
}

// ---------------------------------------------------------------------------
extern "C" void kernel_launch(void* const* d_in, const int* in_sizes, int n_in,
                              void* d_out, int out_size) {
    const float* pred  = (const float*)d_in[0];  // predict_score
    const float* score = (const float*)d_in[1];  // score (0/1)
    int N = in_sizes[0];
    int G = (N + EPB - 1) / EPB;
    if (G > MAXG) G = MAXG;   // problem size is 2^24 -> G = 2048

    k_mask<<<G, 256>>>(score, N);
    k_loss<<<G, 256>>>(pred, N, G);
    k_final<<<1, 256>>>((float*)d_out, G);
}